// round 1
// baseline (speedup 1.0000x reference)
#include <cuda_runtime.h>
#include <math.h>

#define HH 768
#define LAYERS 10
#define WW 10
#define BB 512
#define G4H 3072
#define TB 5120   // WW*BB

// Scratch (device globals: allocation-free rule)
__device__ float g_xin[WW * BB * HH];    // fc0 input, (W,B,H) layout
__device__ float g_x[WW * BB * HH];      // layer activations / h outputs
__device__ float g_gx[WW * BB * G4H];    // gate pre-activations per layer
__device__ float g_c[BB * HH];           // cell state
__device__ float g_xcat[BB * WW * HH];   // fc1 packed input

// C[M,N] = A[M,K] @ Wt[N,K]^T (+bias1+bias2)   when accum==0
// C[M,N] += A[M,K] @ Wt[N,K]^T                 when accum==1
// M,N multiples of 64; K multiple of 8.
__global__ __launch_bounds__(256) void gemm_kernel(
    const float* __restrict__ A, const float* __restrict__ Wt,
    const float* __restrict__ bias1, const float* __restrict__ bias2,
    float* __restrict__ C, int M, int N, int K, int accum)
{
    __shared__ float As[8][64];
    __shared__ float Bs[8][64];
    const int bm = blockIdx.y * 64;
    const int bn = blockIdx.x * 64;
    const int tid = threadIdx.x;
    const int ty = tid >> 4;       // 0..15
    const int tx = tid & 15;       // 0..15
    const int lr = tid >> 2;       // 0..63 : tile row for loads
    const int lk = (tid & 3) * 2;  // 0,2,4,6 : k-pair for loads

    float acc[4][4] = {};

    const float* Arow = A + (size_t)(bm + lr) * K + lk;
    const float* Wrow = Wt + (size_t)(bn + lr) * K + lk;

    for (int k0 = 0; k0 < K; k0 += 8) {
        As[lk][lr]     = Arow[k0];
        As[lk + 1][lr] = Arow[k0 + 1];
        Bs[lk][lr]     = Wrow[k0];
        Bs[lk + 1][lr] = Wrow[k0 + 1];
        __syncthreads();
#pragma unroll
        for (int k = 0; k < 8; k++) {
            float a[4], b[4];
#pragma unroll
            for (int i = 0; i < 4; i++) a[i] = As[k][ty * 4 + i];
#pragma unroll
            for (int j = 0; j < 4; j++) b[j] = Bs[k][tx * 4 + j];
#pragma unroll
            for (int i = 0; i < 4; i++)
#pragma unroll
                for (int j = 0; j < 4; j++)
                    acc[i][j] += a[i] * b[j];
        }
        __syncthreads();
    }

#pragma unroll
    for (int i = 0; i < 4; i++) {
        int row = bm + ty * 4 + i;
        float* Cp = C + (size_t)row * N + bn + tx * 4;
        if (accum) {
#pragma unroll
            for (int j = 0; j < 4; j++) Cp[j] += acc[i][j];
        } else {
#pragma unroll
            for (int j = 0; j < 4; j++) {
                int col = bn + tx * 4 + j;
                float bv = bias1[col];
                if (bias2) bv += bias2[col];
                Cp[j] = acc[i][j] + bv;
            }
        }
    }
}

// (B,W,H) -> (W,B,H)
__global__ void transpose_in_kernel(const float* __restrict__ src, float* __restrict__ dst)
{
    int idx = blockIdx.x * blockDim.x + threadIdx.x;
    if (idx >= WW * BB * HH) return;
    int k = idx % HH;
    int r = idx / HH;       // t*BB + b
    int t = r / BB;
    int b = r % BB;
    dst[idx] = src[((size_t)b * WW + t) * HH + k];
}

// (W,B,H) -> (B, W*H)
__global__ void pack_fc1_kernel(const float* __restrict__ src, float* __restrict__ dst)
{
    int idx = blockIdx.x * blockDim.x + threadIdx.x;
    if (idx >= BB * WW * HH) return;
    int k = idx % HH;
    int r = idx / HH;       // b*WW + t
    int b = r / WW;
    int t = r % WW;
    dst[idx] = src[((size_t)t * BB + b) * HH + k];
}

// gates from gx_t (B,4H); update c; write h to h_out (B,H)
__global__ void gate_kernel(const float* __restrict__ gx_t, float* __restrict__ c,
                            float* __restrict__ h_out, int first)
{
    int idx = blockIdx.x * blockDim.x + threadIdx.x;
    if (idx >= BB * HH) return;
    int b = idx / HH;
    int n = idx % HH;
    const float* g = gx_t + (size_t)b * G4H;
    float gi = g[n];
    float gf = g[n + HH];
    float gg = g[n + 2 * HH];
    float go = g[n + 3 * HH];
    float iv = 1.0f / (1.0f + expf(-gi));
    float fv = 1.0f / (1.0f + expf(-gf));
    float gv = tanhf(gg);
    float ov = 1.0f / (1.0f + expf(-go));
    float cv = first ? (iv * gv) : (fv * c[idx] + iv * gv);
    c[idx] = cv;
    h_out[idx] = ov * tanhf(cv);
}

extern "C" void kernel_launch(void* const* d_in, const int* in_sizes, int n_in,
                              void* d_out, int out_size)
{
    const float* xpos  = (const float*)d_in[0];
    const float* fc0_w = (const float*)d_in[1];
    const float* fc0_b = (const float*)d_in[2];
    const float* w_ih  = (const float*)d_in[3];
    const float* w_hh  = (const float*)d_in[4];
    const float* b_ih  = (const float*)d_in[5];
    const float* b_hh  = (const float*)d_in[6];
    const float* fc1_w = (const float*)d_in[7];
    const float* fc1_b = (const float*)d_in[8];
    float* out = (float*)d_out;

    float *xin, *x, *gx, *c, *xcat;
    cudaGetSymbolAddress((void**)&xin,  g_xin);
    cudaGetSymbolAddress((void**)&x,    g_x);
    cudaGetSymbolAddress((void**)&gx,   g_gx);
    cudaGetSymbolAddress((void**)&c,    g_c);
    cudaGetSymbolAddress((void**)&xcat, g_xcat);

    const int EL_THREADS = 256;
    int nxin = WW * BB * HH;

    // (B,W,H) -> (W,B,H)
    transpose_in_kernel<<<(nxin + EL_THREADS - 1) / EL_THREADS, EL_THREADS>>>(xpos, xin);

    // fc0: x = xin @ fc0_w^T + fc0_b   (TB x H, K=H)
    gemm_kernel<<<dim3(HH / 64, TB / 64), 256>>>(xin, fc0_w, fc0_b, nullptr, x,
                                                 TB, HH, HH, 0);

    for (int l = 0; l < LAYERS; l++) {
        const float* wih = w_ih + (size_t)l * G4H * HH;
        const float* whh = w_hh + (size_t)l * G4H * HH;
        const float* bih = b_ih + (size_t)l * G4H;
        const float* bhh = b_hh + (size_t)l * G4H;

        // gx = x @ wih^T + bih + bhh    (TB x 4H, K=H)
        gemm_kernel<<<dim3(G4H / 64, TB / 64), 256>>>(x, wih, bih, bhh, gx,
                                                      TB, G4H, HH, 0);

        // t = 0: h=c=0, g = gx[0]
        gate_kernel<<<(BB * HH + EL_THREADS - 1) / EL_THREADS, EL_THREADS>>>(
            gx, c, x, 1);

        for (int t = 1; t < WW; t++) {
            // gx[t] += h_{t-1} @ whh^T ; h_{t-1} lives at x + (t-1)*B*H
            gemm_kernel<<<dim3(G4H / 64, BB / 64), 256>>>(
                x + (size_t)(t - 1) * BB * HH, whh, nullptr, nullptr,
                gx + (size_t)t * BB * G4H, BB, G4H, HH, 1);
            gate_kernel<<<(BB * HH + EL_THREADS - 1) / EL_THREADS, EL_THREADS>>>(
                gx + (size_t)t * BB * G4H, c, x + (size_t)t * BB * HH, 0);
        }
    }

    // pack (W,B,H) -> (B, W*H)
    pack_fc1_kernel<<<(BB * WW * HH + EL_THREADS - 1) / EL_THREADS, EL_THREADS>>>(x, xcat);

    // fc1: out = xcat @ fc1_w^T + fc1_b   (B x H, K = W*H)
    gemm_kernel<<<dim3(HH / 64, BB / 64), 256>>>(xcat, fc1_w, fc1_b, nullptr, out,
                                                 BB, HH, WW * HH, 0);
}

// round 2
// speedup vs baseline: 2.5686x; 2.5686x over previous
#include <cuda_runtime.h>
#include <cuda_bf16.h>
#include <math.h>
#include <stdint.h>

#define HH 768
#define LAYERS 10
#define WW 10
#define BB 512
#define G4H 3072
#define TB 5120   // WW*BB

#define KT 32          // K-slab in floats
#define STRIDE 20      // u32 per smem row (16 used + 4 pad -> conflict-free)
#define PLANE (128 * STRIDE)
#define SMEM_BYTES (2 /*stages*/ * 2 /*mats*/ * 2 /*planes*/ * PLANE * 4)

// Scratch (device globals: allocation-free rule)
__device__ float g_xin[WW * BB * HH];
__device__ float g_x[WW * BB * HH];
__device__ float g_gx[WW * BB * G4H];
__device__ float g_c[BB * HH];
__device__ float g_xcat[BB * WW * HH];

__device__ __forceinline__ void split_pack(float e0, float e1,
                                           uint32_t& hi, uint32_t& lo)
{
    // hi/lo each hold 2 bf16: low 16 bits = element k (even), high = k+1
    __nv_bfloat16 h0 = __float2bfloat16_rn(e0);
    __nv_bfloat16 h1 = __float2bfloat16_rn(e1);
    float r0 = e0 - __bfloat162float(h0);
    float r1 = e1 - __bfloat162float(h1);
    __nv_bfloat16 l0 = __float2bfloat16_rn(r0);
    __nv_bfloat16 l1 = __float2bfloat16_rn(r1);
    hi = ((uint32_t)__bfloat16_as_ushort(h1) << 16) | __bfloat16_as_ushort(h0);
    lo = ((uint32_t)__bfloat16_as_ushort(l1) << 16) | __bfloat16_as_ushort(l0);
}

__device__ __forceinline__ void mma_bf16(float* c, const uint32_t* a, const uint32_t* b)
{
    asm volatile(
        "mma.sync.aligned.m16n8k16.row.col.f32.bf16.bf16.f32 "
        "{%0,%1,%2,%3}, {%4,%5,%6,%7}, {%8,%9}, {%0,%1,%2,%3};"
        : "+f"(c[0]), "+f"(c[1]), "+f"(c[2]), "+f"(c[3])
        : "r"(a[0]), "r"(a[1]), "r"(a[2]), "r"(a[3]), "r"(b[0]), "r"(b[1]));
}

// C[M,N] (+)= A[M,K] @ Wt[N,K]^T (+ bias1 (+bias2))
// bf16x2 split, 3 mma products -> ~fp32 accuracy.
// M,N multiples of 128; K multiple of 32.
__global__ __launch_bounds__(256) void gemm_bf16x2(
    const float* __restrict__ A, const float* __restrict__ Wt,
    const float* __restrict__ bias1, const float* __restrict__ bias2,
    float* __restrict__ C, int M, int N, int K, int accum)
{
    extern __shared__ uint32_t sm[];
    // layout: [stage][mat(A=0,W=1)][plane(hi=0,lo=1)][PLANE]
    const int tid = threadIdx.x;
    const int lane = tid & 31;
    const int wid = tid >> 5;
    const int wm = wid >> 2;          // 0..1
    const int wn = wid & 3;           // 0..3
    const int bm = blockIdx.y * 128;
    const int bn = blockIdx.x * 128;
    const int q = lane >> 2;          // 0..7
    const int r = lane & 3;           // 0..3

    const int ns = K / KT;

    float acc[4][4][4];
#pragma unroll
    for (int i = 0; i < 4; i++)
#pragma unroll
        for (int j = 0; j < 4; j++)
#pragma unroll
            for (int v = 0; v < 4; v++) acc[i][j][v] = 0.f;

    // loader mapping: float4 index f = tid + i*256 -> m = f>>3, kv = f&7
    float4 areg[4], breg[4];

    auto ldg_slab = [&](int k0) {
#pragma unroll
        for (int i = 0; i < 4; i++) {
            int f = tid + i * 256;
            int m = f >> 3, kv = f & 7;
            areg[i] = *(const float4*)(A + (size_t)(bm + m) * K + k0 + kv * 4);
            breg[i] = *(const float4*)(Wt + (size_t)(bn + m) * K + k0 + kv * 4);
        }
    };

    auto sts_slab = [&](int stage) {
        uint32_t* Ah = sm + ((stage * 2 + 0) * 2 + 0) * PLANE;
        uint32_t* Al = sm + ((stage * 2 + 0) * 2 + 1) * PLANE;
        uint32_t* Bh = sm + ((stage * 2 + 1) * 2 + 0) * PLANE;
        uint32_t* Bl = sm + ((stage * 2 + 1) * 2 + 1) * PLANE;
#pragma unroll
        for (int i = 0; i < 4; i++) {
            int f = tid + i * 256;
            int m = f >> 3, kv = f & 7;
            int off = m * STRIDE + kv * 2;
            uint32_t h0, l0, h1, l1;
            split_pack(areg[i].x, areg[i].y, h0, l0);
            split_pack(areg[i].z, areg[i].w, h1, l1);
            *(uint2*)(Ah + off) = make_uint2(h0, h1);
            *(uint2*)(Al + off) = make_uint2(l0, l1);
            split_pack(breg[i].x, breg[i].y, h0, l0);
            split_pack(breg[i].z, breg[i].w, h1, l1);
            *(uint2*)(Bh + off) = make_uint2(h0, h1);
            *(uint2*)(Bl + off) = make_uint2(l0, l1);
        }
    };

    auto compute = [&](int stage) {
        const uint32_t* Ah = sm + ((stage * 2 + 0) * 2 + 0) * PLANE;
        const uint32_t* Al = sm + ((stage * 2 + 0) * 2 + 1) * PLANE;
        const uint32_t* Bh = sm + ((stage * 2 + 1) * 2 + 0) * PLANE;
        const uint32_t* Bl = sm + ((stage * 2 + 1) * 2 + 1) * PLANE;
#pragma unroll
        for (int k16 = 0; k16 < 2; k16++) {
            int kp = k16 * 8;
            uint32_t bh[4][2], bl[4][2];
#pragma unroll
            for (int ni = 0; ni < 4; ni++) {
                int n = wn * 32 + ni * 8 + q;
                bh[ni][0] = Bh[n * STRIDE + kp + r];
                bh[ni][1] = Bh[n * STRIDE + kp + r + 4];
                bl[ni][0] = Bl[n * STRIDE + kp + r];
                bl[ni][1] = Bl[n * STRIDE + kp + r + 4];
            }
#pragma unroll
            for (int mi = 0; mi < 4; mi++) {
                int m0 = wm * 64 + mi * 16 + q;
                uint32_t ah[4], al[4];
                ah[0] = Ah[m0 * STRIDE + kp + r];
                ah[1] = Ah[(m0 + 8) * STRIDE + kp + r];
                ah[2] = Ah[m0 * STRIDE + kp + r + 4];
                ah[3] = Ah[(m0 + 8) * STRIDE + kp + r + 4];
                al[0] = Al[m0 * STRIDE + kp + r];
                al[1] = Al[(m0 + 8) * STRIDE + kp + r];
                al[2] = Al[m0 * STRIDE + kp + r + 4];
                al[3] = Al[(m0 + 8) * STRIDE + kp + r + 4];
#pragma unroll
                for (int ni = 0; ni < 4; ni++) {
                    mma_bf16(acc[mi][ni], ah, bh[ni]);   // hi*hi
                    mma_bf16(acc[mi][ni], ah, bl[ni]);   // hi*lo
                    mma_bf16(acc[mi][ni], al, bh[ni]);   // lo*hi
                }
            }
        }
    };

    // prologue: slab 0
    ldg_slab(0);
    sts_slab(0);
    __syncthreads();

    for (int s = 0; s < ns; s++) {
        if (s + 1 < ns) ldg_slab((s + 1) * KT);
        compute(s & 1);
        if (s + 1 < ns) {
            sts_slab((s + 1) & 1);
        }
        __syncthreads();
    }

    // epilogue
#pragma unroll
    for (int mi = 0; mi < 4; mi++) {
#pragma unroll
        for (int ni = 0; ni < 4; ni++) {
            int m0 = bm + wm * 64 + mi * 16 + q;
            int n0 = bn + wn * 32 + ni * 8 + r * 2;
            float2* p0 = (float2*)(C + (size_t)m0 * N + n0);
            float2* p1 = (float2*)(C + (size_t)(m0 + 8) * N + n0);
            float* a = acc[mi][ni];
            if (accum) {
                float2 v0 = *p0, v1 = *p1;
                v0.x += a[0]; v0.y += a[1];
                v1.x += a[2]; v1.y += a[3];
                *p0 = v0; *p1 = v1;
            } else {
                float bv0 = bias1[n0], bv1 = bias1[n0 + 1];
                if (bias2) { bv0 += bias2[n0]; bv1 += bias2[n0 + 1]; }
                *p0 = make_float2(a[0] + bv0, a[1] + bv1);
                *p1 = make_float2(a[2] + bv0, a[3] + bv1);
            }
        }
    }
}

// (B,W,H) -> (W,B,H)
__global__ void transpose_in_kernel(const float* __restrict__ src, float* __restrict__ dst)
{
    int idx = blockIdx.x * blockDim.x + threadIdx.x;
    if (idx >= WW * BB * HH) return;
    int k = idx % HH;
    int r = idx / HH;
    int t = r / BB;
    int b = r % BB;
    dst[idx] = src[((size_t)b * WW + t) * HH + k];
}

// (W,B,H) -> (B, W*H)
__global__ void pack_fc1_kernel(const float* __restrict__ src, float* __restrict__ dst)
{
    int idx = blockIdx.x * blockDim.x + threadIdx.x;
    if (idx >= BB * WW * HH) return;
    int k = idx % HH;
    int r = idx / HH;
    int b = r / WW;
    int t = r % WW;
    dst[idx] = src[((size_t)t * BB + b) * HH + k];
}

// vectorized gates: 4 consecutive n per thread
__global__ void gate_kernel(const float* __restrict__ gx_t, float* __restrict__ c,
                            float* __restrict__ h_out, int first)
{
    int idx = blockIdx.x * blockDim.x + threadIdx.x;   // over BB*HH/4
    if (idx >= BB * HH / 4) return;
    int b = idx / (HH / 4);
    int n4 = (idx % (HH / 4)) * 4;
    const float* g = gx_t + (size_t)b * G4H;
    float4 gi = *(const float4*)(g + n4);
    float4 gf = *(const float4*)(g + n4 + HH);
    float4 gg = *(const float4*)(g + n4 + 2 * HH);
    float4 go = *(const float4*)(g + n4 + 3 * HH);
    float4 cv;
    float4 cold = first ? make_float4(0, 0, 0, 0) : *(float4*)(c + (size_t)b * HH + n4);
    float4 hv;
#pragma unroll
    for (int j = 0; j < 4; j++) {
        float i_ = ((float*)&gi)[j];
        float f_ = ((float*)&gf)[j];
        float g_ = ((float*)&gg)[j];
        float o_ = ((float*)&go)[j];
        float iv = 1.0f / (1.0f + expf(-i_));
        float fv = 1.0f / (1.0f + expf(-f_));
        float gv = tanhf(g_);
        float ov = 1.0f / (1.0f + expf(-o_));
        float cc = fv * ((float*)&cold)[j] + iv * gv;
        ((float*)&cv)[j] = cc;
        ((float*)&hv)[j] = ov * tanhf(cc);
    }
    *(float4*)(c + (size_t)b * HH + n4) = cv;
    *(float4*)(h_out + (size_t)b * HH + n4) = hv;
}

extern "C" void kernel_launch(void* const* d_in, const int* in_sizes, int n_in,
                              void* d_out, int out_size)
{
    const float* xpos  = (const float*)d_in[0];
    const float* fc0_w = (const float*)d_in[1];
    const float* fc0_b = (const float*)d_in[2];
    const float* w_ih  = (const float*)d_in[3];
    const float* w_hh  = (const float*)d_in[4];
    const float* b_ih  = (const float*)d_in[5];
    const float* b_hh  = (const float*)d_in[6];
    const float* fc1_w = (const float*)d_in[7];
    const float* fc1_b = (const float*)d_in[8];
    float* out = (float*)d_out;

    float *xin, *x, *gx, *c, *xcat;
    cudaGetSymbolAddress((void**)&xin,  g_xin);
    cudaGetSymbolAddress((void**)&x,    g_x);
    cudaGetSymbolAddress((void**)&gx,   g_gx);
    cudaGetSymbolAddress((void**)&c,    g_c);
    cudaGetSymbolAddress((void**)&xcat, g_xcat);

    static bool attr_done = false;
    if (!attr_done) {
        cudaFuncSetAttribute(gemm_bf16x2,
                             cudaFuncAttributeMaxDynamicSharedMemorySize, SMEM_BYTES);
        attr_done = true;
    }

    const int EL = 256;
    int nxin = WW * BB * HH;
    int ngate = BB * HH / 4;

    transpose_in_kernel<<<(nxin + EL - 1) / EL, EL>>>(xpos, xin);

    // fc0: x = xin @ fc0_w^T + fc0_b   (TB x H, K=H)
    gemm_bf16x2<<<dim3(HH / 128, TB / 128), 256, SMEM_BYTES>>>(
        xin, fc0_w, fc0_b, nullptr, x, TB, HH, HH, 0);

    for (int l = 0; l < LAYERS; l++) {
        const float* wih = w_ih + (size_t)l * G4H * HH;
        const float* whh = w_hh + (size_t)l * G4H * HH;
        const float* bih = b_ih + (size_t)l * G4H;
        const float* bhh = b_hh + (size_t)l * G4H;

        // gx = x @ wih^T + bih + bhh   (TB x 4H, K=H)
        gemm_bf16x2<<<dim3(G4H / 128, TB / 128), 256, SMEM_BYTES>>>(
            x, wih, bih, bhh, gx, TB, G4H, HH, 0);

        gate_kernel<<<(ngate + EL - 1) / EL, EL>>>(gx, c, x, 1);

        for (int t = 1; t < WW; t++) {
            gemm_bf16x2<<<dim3(G4H / 128, BB / 128), 256, SMEM_BYTES>>>(
                x + (size_t)(t - 1) * BB * HH, whh, nullptr, nullptr,
                gx + (size_t)t * BB * G4H, BB, G4H, HH, 1);
            gate_kernel<<<(ngate + EL - 1) / EL, EL>>>(
                gx + (size_t)t * BB * G4H, c, x + (size_t)t * BB * HH, 0);
        }
    }

    pack_fc1_kernel<<<(BB * WW * HH + EL - 1) / EL, EL>>>(x, xcat);

    // fc1: out = xcat @ fc1_w^T + fc1_b   (B x H, K = W*H)
    gemm_bf16x2<<<dim3(HH / 128, BB / 128), 256, SMEM_BYTES>>>(
        xcat, fc1_w, fc1_b, nullptr, out, BB, HH, WW * HH, 0);
}

// round 3
// speedup vs baseline: 2.5948x; 1.0102x over previous
#include <cuda_runtime.h>
#include <cuda_bf16.h>
#include <math.h>
#include <stdint.h>

#define HH 768
#define LAYERS 10
#define WW 10
#define BB 512
#define G4H 3072
#define TB 5120   // WW*BB

#define KT 32          // K-slab in elements
#define STRIDE 20      // u32 per smem row (16 used + 4 pad -> conflict-free)
#define PLANE (128 * STRIDE)           // u32 per plane
#define SMEM_BYTES (2 /*stages*/ * 4 /*planes*/ * PLANE * 4)

typedef __nv_bfloat16 bf16;

// ---------------- scratch (device globals; allocation-free rule) -------------
__device__ bf16  g_ainhi[TB * HH], g_ainlo[TB * HH];       // fc0 input split
__device__ bf16  g_xhi[TB * HH],   g_xlo[TB * HH];         // activations / h split
__device__ float g_gx[TB * G4H];                           // gate preacts
__device__ float g_c[BB * HH];                             // cell state
__device__ bf16  g_xcathi[BB * WW * HH], g_xcatlo[BB * WW * HH];
__device__ bf16  g_fc0whi[HH * HH],      g_fc0wlo[HH * HH];
__device__ bf16  g_fc1whi[HH * WW * HH], g_fc1wlo[HH * WW * HH];
__device__ bf16  g_wihhi[LAYERS * G4H * HH], g_wihlo[LAYERS * G4H * HH];
__device__ bf16  g_whhhi[LAYERS * G4H * HH], g_whhlo[LAYERS * G4H * HH];
__device__ float g_bcomb[LAYERS * G4H];

// ---------------- helpers ----------------------------------------------------
__device__ __forceinline__ void split1(float v, bf16& h, bf16& l)
{
    h = __float2bfloat16_rn(v);
    l = __float2bfloat16_rn(v - __bfloat162float(h));
}

__device__ __forceinline__ void cpasync16(void* dst, const void* src)
{
    uint32_t s = (uint32_t)__cvta_generic_to_shared(dst);
    asm volatile("cp.async.cg.shared.global [%0], [%1], 16;\n" :: "r"(s), "l"(src));
}
__device__ __forceinline__ void cp_commit() { asm volatile("cp.async.commit_group;\n"); }

__device__ __forceinline__ void mma_bf16(float* c, const uint32_t* a, const uint32_t* b)
{
    asm volatile(
        "mma.sync.aligned.m16n8k16.row.col.f32.bf16.bf16.f32 "
        "{%0,%1,%2,%3}, {%4,%5,%6,%7}, {%8,%9}, {%0,%1,%2,%3};"
        : "+f"(c[0]), "+f"(c[1]), "+f"(c[2]), "+f"(c[3])
        : "r"(a[0]), "r"(a[1]), "r"(a[2]), "r"(a[3]), "r"(b[0]), "r"(b[1]));
}

__device__ __forceinline__ float sigm(float x) { return 1.0f / (1.0f + expf(-x)); }

// ---------------- GEMM: C = A @ Wt^T, bf16x2 split (3 mma), cp.async ---------
// MODE 0: C fp32 = acc + bias
// MODE 1: (Chi,Clo) split bf16 = acc + bias
// MODE 2: fused LSTM cell: g = acc + gx_tile; gates; c update; h -> (Chi,Clo)
//         (gate-interleaved col layout: col j = n*4 + gate)
template <int MODE>
__global__ __launch_bounds__(256) void gemm_bf16(
    const bf16* __restrict__ Ahi, const bf16* __restrict__ Alo,
    const bf16* __restrict__ Bhi, const bf16* __restrict__ Blo,
    const float* __restrict__ bias,
    float* __restrict__ C,
    bf16* __restrict__ Chi, bf16* __restrict__ Clo,
    const float* __restrict__ gx, float* __restrict__ cstate, int first,
    int M, int N, int K)
{
    extern __shared__ uint32_t sm[];
    const int tid = threadIdx.x;
    const int lane = tid & 31;
    const int wid = tid >> 5;
    const int wm = wid >> 2;
    const int wn = wid & 3;
    const int bm = blockIdx.y * 128;
    const int bn = blockIdx.x * 128;
    const int q = lane >> 2;
    const int r = lane & 3;
    const int ns = K / KT;

    float acc[4][4][4];
#pragma unroll
    for (int i = 0; i < 4; i++)
#pragma unroll
        for (int j = 0; j < 4; j++)
#pragma unroll
            for (int v = 0; v < 4; v++) acc[i][j][v] = 0.f;

    auto issue = [&](int slab, int stage) {
        int k0 = slab * KT;
        uint32_t* base = sm + stage * 4 * PLANE;
#pragma unroll
        for (int i = 0; i < 2; i++) {
            int f = tid + i * 256;
            int m = f >> 2, cc = f & 3;
            size_t ga = (size_t)(bm + m) * K + k0 + cc * 8;
            size_t gb = (size_t)(bn + m) * K + k0 + cc * 8;
            int so = m * STRIDE + cc * 4;
            cpasync16(base + 0 * PLANE + so, Ahi + ga);
            cpasync16(base + 1 * PLANE + so, Alo + ga);
            cpasync16(base + 2 * PLANE + so, Bhi + gb);
            cpasync16(base + 3 * PLANE + so, Blo + gb);
        }
        cp_commit();
    };

    auto compute = [&](int stage) {
        const uint32_t* Ah = sm + stage * 4 * PLANE + 0 * PLANE;
        const uint32_t* Al = sm + stage * 4 * PLANE + 1 * PLANE;
        const uint32_t* Bh = sm + stage * 4 * PLANE + 2 * PLANE;
        const uint32_t* Bl = sm + stage * 4 * PLANE + 3 * PLANE;
#pragma unroll
        for (int k16 = 0; k16 < 2; k16++) {
            int kp = k16 * 8;
            uint32_t bh[4][2], bl[4][2];
#pragma unroll
            for (int ni = 0; ni < 4; ni++) {
                int n = wn * 32 + ni * 8 + q;
                bh[ni][0] = Bh[n * STRIDE + kp + r];
                bh[ni][1] = Bh[n * STRIDE + kp + r + 4];
                bl[ni][0] = Bl[n * STRIDE + kp + r];
                bl[ni][1] = Bl[n * STRIDE + kp + r + 4];
            }
#pragma unroll
            for (int mi = 0; mi < 4; mi++) {
                int m0 = wm * 64 + mi * 16 + q;
                uint32_t ah[4], al[4];
                ah[0] = Ah[m0 * STRIDE + kp + r];
                ah[1] = Ah[(m0 + 8) * STRIDE + kp + r];
                ah[2] = Ah[m0 * STRIDE + kp + r + 4];
                ah[3] = Ah[(m0 + 8) * STRIDE + kp + r + 4];
                al[0] = Al[m0 * STRIDE + kp + r];
                al[1] = Al[(m0 + 8) * STRIDE + kp + r];
                al[2] = Al[m0 * STRIDE + kp + r + 4];
                al[3] = Al[(m0 + 8) * STRIDE + kp + r + 4];
#pragma unroll
                for (int ni = 0; ni < 4; ni++) {
                    mma_bf16(acc[mi][ni], ah, bh[ni]);
                    mma_bf16(acc[mi][ni], ah, bl[ni]);
                    mma_bf16(acc[mi][ni], al, bh[ni]);
                }
            }
        }
    };

    if (ns > 0) {
        issue(0, 0);
        if (ns > 1) issue(1, 1); else cp_commit();
        for (int s = 0; s < ns; s++) {
            if (s + 1 < ns) asm volatile("cp.async.wait_group 1;\n");
            else            asm volatile("cp.async.wait_group 0;\n");
            __syncthreads();
            compute(s & 1);
            __syncthreads();
            if (s + 2 < ns) issue(s + 2, s & 1);
        }
    }

    // ----------------- epilogue -----------------
#pragma unroll
    for (int mi = 0; mi < 4; mi++) {
#pragma unroll
        for (int ni = 0; ni < 4; ni++) {
            int m0 = bm + wm * 64 + mi * 16 + q;
            int n0 = bn + wn * 32 + ni * 8 + r * 2;
            float* a = acc[mi][ni];

            if (MODE == 0) {
                float bv0 = bias[n0], bv1 = bias[n0 + 1];
                *(float2*)(C + (size_t)m0 * N + n0) =
                    make_float2(a[0] + bv0, a[1] + bv1);
                *(float2*)(C + (size_t)(m0 + 8) * N + n0) =
                    make_float2(a[2] + bv0, a[3] + bv1);
            } else if (MODE == 1) {
                float bv0 = bias[n0], bv1 = bias[n0 + 1];
                float v00 = a[0] + bv0, v01 = a[1] + bv1;
                float v10 = a[2] + bv0, v11 = a[3] + bv1;
                bf16 h0, l0, h1, l1;
                split1(v00, h0, l0); split1(v01, h1, l1);
                *(__nv_bfloat162*)(Chi + (size_t)m0 * N + n0) = __nv_bfloat162(h0, h1);
                *(__nv_bfloat162*)(Clo + (size_t)m0 * N + n0) = __nv_bfloat162(l0, l1);
                split1(v10, h0, l0); split1(v11, h1, l1);
                *(__nv_bfloat162*)(Chi + (size_t)(m0 + 8) * N + n0) = __nv_bfloat162(h0, h1);
                *(__nv_bfloat162*)(Clo + (size_t)(m0 + 8) * N + n0) = __nv_bfloat162(l0, l1);
            } else {
                // add gx tile
                float2 g0 = *(const float2*)(gx + (size_t)m0 * N + n0);
                float2 g1 = *(const float2*)(gx + (size_t)(m0 + 8) * N + n0);
                float a0 = a[0] + g0.x, a1 = a[1] + g0.y;
                float a2 = a[2] + g1.x, a3 = a[3] + g1.y;
                // lane pair (r even: i,f) / (r odd: g,o) for same n
                float p0 = __shfl_xor_sync(0xFFFFFFFFu, a0, 1);
                float p1 = __shfl_xor_sync(0xFFFFFFFFu, a1, 1);
                float p2 = __shfl_xor_sync(0xFFFFFFFFu, a2, 1);
                float p3 = __shfl_xor_sync(0xFFFFFFFFu, a3, 1);
                if ((r & 1) == 0) {
                    int n = n0 >> 2;   // real hidden index
#pragma unroll
                    for (int rr = 0; rr < 2; rr++) {
                        int m = m0 + rr * 8;
                        float gi = rr ? a2 : a0;
                        float gf = rr ? a3 : a1;
                        float gg = rr ? p2 : p0;
                        float go = rr ? p3 : p1;
                        float cold = first ? 0.f : cstate[(size_t)m * HH + n];
                        float cn = sigm(gf) * cold + sigm(gi) * tanhf(gg);
                        cstate[(size_t)m * HH + n] = cn;
                        float h = sigm(go) * tanhf(cn);
                        bf16 hh, hl;
                        split1(h, hh, hl);
                        Chi[(size_t)m * HH + n] = hh;
                        Clo[(size_t)m * HH + n] = hl;
                    }
                }
            }
        }
    }
}

// ---------------- prep / reshape kernels -------------------------------------
__global__ void split_plain(const float* __restrict__ w, bf16* __restrict__ hi,
                            bf16* __restrict__ lo, int n)
{
    int i = blockIdx.x * blockDim.x + threadIdx.x;
    if (i >= n) return;
    split1(w[i], hi[i], lo[i]);
}

// row j = n*4+g  <-  row g*HH+n   (per layer), split to bf16 hi/lo
__global__ void permute_split_gates(const float* __restrict__ w,
                                    bf16* __restrict__ hi, bf16* __restrict__ lo)
{
    int i = blockIdx.x * blockDim.x + threadIdx.x;
    if (i >= LAYERS * G4H * HH) return;
    int k = i % HH;
    int j = (i / HH) % G4H;
    int l = i / (HH * G4H);
    int n = j >> 2, g = j & 3;
    float v = w[(size_t)l * G4H * HH + (size_t)(g * HH + n) * HH + k];
    split1(v, hi[i], lo[i]);
}

__global__ void combine_bias(const float* __restrict__ bih,
                             const float* __restrict__ bhh, float* __restrict__ bc)
{
    int i = blockIdx.x * blockDim.x + threadIdx.x;
    if (i >= LAYERS * G4H) return;
    int j = i % G4H;
    int l = i / G4H;
    int n = j >> 2, g = j & 3;
    bc[i] = bih[l * G4H + g * HH + n] + bhh[l * G4H + g * HH + n];
}

// (B,W,H) fp32 -> (W*B, H) split bf16
__global__ void transpose_split(const float* __restrict__ src,
                                bf16* __restrict__ hi, bf16* __restrict__ lo)
{
    int i = blockIdx.x * blockDim.x + threadIdx.x;
    if (i >= TB * HH) return;
    int k = i % HH;
    int row = i / HH;          // t*BB + b
    int t = row / BB, b = row % BB;
    split1(src[((size_t)b * WW + t) * HH + k], hi[i], lo[i]);
}

// (W,B,H) split -> (B, W*H) split
__global__ void pack_split(const bf16* __restrict__ xhi, const bf16* __restrict__ xlo,
                           bf16* __restrict__ chi, bf16* __restrict__ clo)
{
    int i = blockIdx.x * blockDim.x + threadIdx.x;
    if (i >= BB * WW * HH) return;
    int b = i / (WW * HH);
    int tk = i % (WW * HH);
    int t = tk / HH, k = tk % HH;
    size_t s = ((size_t)t * BB + b) * HH + k;
    chi[i] = xhi[s];
    clo[i] = xlo[s];
}

// ---------------- host -------------------------------------------------------
extern "C" void kernel_launch(void* const* d_in, const int* in_sizes, int n_in,
                              void* d_out, int out_size)
{
    const float* xpos  = (const float*)d_in[0];
    const float* fc0_w = (const float*)d_in[1];
    const float* fc0_b = (const float*)d_in[2];
    const float* w_ih  = (const float*)d_in[3];
    const float* w_hh  = (const float*)d_in[4];
    const float* b_ih  = (const float*)d_in[5];
    const float* b_hh  = (const float*)d_in[6];
    const float* fc1_w = (const float*)d_in[7];
    const float* fc1_b = (const float*)d_in[8];
    float* out = (float*)d_out;

    bf16 *ainhi, *ainlo, *xhi, *xlo, *xcathi, *xcatlo;
    bf16 *fc0whi, *fc0wlo, *fc1whi, *fc1wlo, *wihhi, *wihlo, *whhhi, *whhlo;
    float *gx, *c, *bcomb;
    cudaGetSymbolAddress((void**)&ainhi, g_ainhi);
    cudaGetSymbolAddress((void**)&ainlo, g_ainlo);
    cudaGetSymbolAddress((void**)&xhi,   g_xhi);
    cudaGetSymbolAddress((void**)&xlo,   g_xlo);
    cudaGetSymbolAddress((void**)&xcathi, g_xcathi);
    cudaGetSymbolAddress((void**)&xcatlo, g_xcatlo);
    cudaGetSymbolAddress((void**)&fc0whi, g_fc0whi);
    cudaGetSymbolAddress((void**)&fc0wlo, g_fc0wlo);
    cudaGetSymbolAddress((void**)&fc1whi, g_fc1whi);
    cudaGetSymbolAddress((void**)&fc1wlo, g_fc1wlo);
    cudaGetSymbolAddress((void**)&wihhi, g_wihhi);
    cudaGetSymbolAddress((void**)&wihlo, g_wihlo);
    cudaGetSymbolAddress((void**)&whhhi, g_whhhi);
    cudaGetSymbolAddress((void**)&whhlo, g_whhlo);
    cudaGetSymbolAddress((void**)&gx,    g_gx);
    cudaGetSymbolAddress((void**)&c,     g_c);
    cudaGetSymbolAddress((void**)&bcomb, g_bcomb);

    static bool attr_done = false;
    if (!attr_done) {
        cudaFuncSetAttribute(gemm_bf16<0>, cudaFuncAttributeMaxDynamicSharedMemorySize, SMEM_BYTES);
        cudaFuncSetAttribute(gemm_bf16<1>, cudaFuncAttributeMaxDynamicSharedMemorySize, SMEM_BYTES);
        cudaFuncSetAttribute(gemm_bf16<2>, cudaFuncAttributeMaxDynamicSharedMemorySize, SMEM_BYTES);
        attr_done = true;
    }

    const int EL = 256;

    // ---- prep (runs inside graph; cheap, amortized) ----
    split_plain<<<(HH * HH + EL - 1) / EL, EL>>>(fc0_w, fc0whi, fc0wlo, HH * HH);
    split_plain<<<(HH * WW * HH + EL - 1) / EL, EL>>>(fc1_w, fc1whi, fc1wlo, HH * WW * HH);
    permute_split_gates<<<(LAYERS * G4H * HH + EL - 1) / EL, EL>>>(w_ih, wihhi, wihlo);
    permute_split_gates<<<(LAYERS * G4H * HH + EL - 1) / EL, EL>>>(w_hh, whhhi, whhlo);
    combine_bias<<<(LAYERS * G4H + EL - 1) / EL, EL>>>(b_ih, b_hh, bcomb);
    transpose_split<<<(TB * HH + EL - 1) / EL, EL>>>(xpos, ainhi, ainlo);

    // ---- fc0: x = xin @ fc0_w^T + b  -> split x ----
    gemm_bf16<1><<<dim3(HH / 128, TB / 128), 256, SMEM_BYTES>>>(
        ainhi, ainlo, fc0whi, fc0wlo, fc0_b,
        nullptr, xhi, xlo, nullptr, nullptr, 0, TB, HH, HH);

    for (int l = 0; l < LAYERS; l++) {
        const bf16* wih_h = wihhi + (size_t)l * G4H * HH;
        const bf16* wih_l = wihlo + (size_t)l * G4H * HH;
        const bf16* whh_h = whhhi + (size_t)l * G4H * HH;
        const bf16* whh_l = whhlo + (size_t)l * G4H * HH;
        const float* bl_  = bcomb + (size_t)l * G4H;

        // gx = x @ wih^T + (bih+bhh)   (interleaved cols)
        gemm_bf16<0><<<dim3(G4H / 128, TB / 128), 256, SMEM_BYTES>>>(
            xhi, xlo, wih_h, wih_l, bl_,
            gx, nullptr, nullptr, nullptr, nullptr, 0, TB, G4H, HH);

        // t = 0: epilogue-only (K=0)
        gemm_bf16<2><<<dim3(G4H / 128, BB / 128), 256, SMEM_BYTES>>>(
            nullptr, nullptr, nullptr, nullptr, nullptr,
            nullptr, xhi, xlo, gx, c, 1, BB, G4H, 0);

        for (int t = 1; t < WW; t++) {
            gemm_bf16<2><<<dim3(G4H / 128, BB / 128), 256, SMEM_BYTES>>>(
                xhi + (size_t)(t - 1) * BB * HH, xlo + (size_t)(t - 1) * BB * HH,
                whh_h, whh_l, nullptr,
                nullptr, xhi + (size_t)t * BB * HH, xlo + (size_t)t * BB * HH,
                gx + (size_t)t * BB * G4H, c, 0, BB, G4H, HH);
        }
    }

    pack_split<<<(BB * WW * HH + EL - 1) / EL, EL>>>(xhi, xlo, xcathi, xcatlo);

    // fc1: out = xcat @ fc1_w^T + b  (fp32 out)
    gemm_bf16<0><<<dim3(HH / 128, BB / 128), 256, SMEM_BYTES>>>(
        xcathi, xcatlo, fc1whi, fc1wlo, fc1_b,
        out, nullptr, nullptr, nullptr, nullptr, 0, BB, HH, WW * HH);
}

// round 9
// speedup vs baseline: 2.9374x; 1.1320x over previous
#include <cuda_runtime.h>
#include <cuda_bf16.h>
#include <math.h>
#include <stdint.h>

#define HH 768
#define LAYERS 10
#define WW 10
#define BB 512
#define G4H 3072
#define TB 5120          // WW*BB
#define KFC1 (WW*HH)     // 7680
#define SPLITK 12

#define KT 32          // K-slab in elements
#define STRIDE 20      // u32 per smem row (16 used + 4 pad; ldmatrix conflict-free)
#define PLANE (128 * STRIDE)           // u32 per plane
#define SMEM_BYTES (2 /*stages*/ * 4 /*planes*/ * PLANE * 4)   // 81920

typedef __nv_bfloat16 bf16;

// ---------------- scratch (device globals; allocation-free rule) -------------
__device__ bf16  g_xAhi[TB * HH], g_xAlo[TB * HH];
__device__ bf16  g_xBhi[TB * HH], g_xBlo[TB * HH];
__device__ float g_gx[TB * G4H];
__device__ float g_c[BB * HH];
__device__ bf16  g_xcathi[BB * KFC1], g_xcatlo[BB * KFC1];   // also fc0 input temp
__device__ bf16  g_fc0whi[HH * HH],   g_fc0wlo[HH * HH];
__device__ bf16  g_fc1whi[HH * KFC1], g_fc1wlo[HH * KFC1];
__device__ bf16  g_wihhi[LAYERS * G4H * HH], g_wihlo[LAYERS * G4H * HH];
__device__ bf16  g_whhhi[LAYERS * G4H * HH], g_whhlo[LAYERS * G4H * HH];
__device__ float g_bcomb[LAYERS * G4H];
__device__ float g_part[SPLITK * BB * HH];

// ---------------- helpers ----------------------------------------------------
__device__ __forceinline__ void split1(float v, bf16& h, bf16& l)
{
    h = __float2bfloat16_rn(v);
    l = __float2bfloat16_rn(v - __bfloat162float(h));
}

__device__ __forceinline__ float sigm(float x) { return 1.0f / (1.0f + expf(-x)); }

__device__ __forceinline__ void cpasync16(void* dst, const void* src)
{
    uint32_t s = (uint32_t)__cvta_generic_to_shared(dst);
    asm volatile("cp.async.cg.shared.global [%0], [%1], 16;\n" :: "r"(s), "l"(src));
}
__device__ __forceinline__ void cp_commit() { asm volatile("cp.async.commit_group;\n"); }

__device__ __forceinline__ void mma_bf16(float* c, const uint32_t* a, const uint32_t* b)
{
    asm volatile(
        "mma.sync.aligned.m16n8k16.row.col.f32.bf16.bf16.f32 "
        "{%0,%1,%2,%3}, {%4,%5,%6,%7}, {%8,%9}, {%0,%1,%2,%3};"
        : "+f"(c[0]), "+f"(c[1]), "+f"(c[2]), "+f"(c[3])
        : "r"(a[0]), "r"(a[1]), "r"(a[2]), "r"(a[3]), "r"(b[0]), "r"(b[1]));
}

__device__ __forceinline__ void ldsm4(uint32_t* r, uint32_t saddr)
{
    asm volatile("ldmatrix.sync.aligned.m8n8.x4.shared.b16 {%0,%1,%2,%3}, [%4];"
                 : "=r"(r[0]), "=r"(r[1]), "=r"(r[2]), "=r"(r[3]) : "r"(saddr));
}

// ---------------- GEMM: C = A @ Wt^T, bf16x2 split (3 mma), cp.async + ldmatrix
// MODE 1: (Chi,Clo) split bf16 = acc + bias                       (fc0)
// MODE 2: fused LSTM cell: g = acc + gx_tile (bias already in gx) (recurrent)
// MODE 3: rows<BB fused cell first=1 (g = acc + bias); rows>=BB: gx = acc + bias
// MODE 4: raw fp32 partial store (split-K via blockIdx.z)         (fc1)
template <int MODE>
__global__ __launch_bounds__(256, 2) void gemm_bf16(
    const bf16* __restrict__ Ahi, const bf16* __restrict__ Alo,
    const bf16* __restrict__ Bhi, const bf16* __restrict__ Blo,
    const float* __restrict__ bias,
    float* __restrict__ Cf,
    bf16* __restrict__ Chi, bf16* __restrict__ Clo,
    const float* __restrict__ gx, float* __restrict__ cstate, int first,
    int M, int N, int K, int nsplit)
{
    extern __shared__ uint32_t sm[];
    const int tid = threadIdx.x;
    const int lane = tid & 31;
    const int wid = tid >> 5;
    const int wm = wid >> 2;          // 0..1
    const int wn = wid & 3;           // 0..3
    const int bm = blockIdx.y * 128;
    const int bn = blockIdx.x * 128;
    const int q = lane >> 2;
    const int r = lane & 3;

    const int NS = K / KT;
    const int NSLABS = NS / nsplit;
    const int s0 = blockIdx.z * NSLABS;

    // ldmatrix per-lane address components
    const int lrowA = ((lane >> 3) & 1) * 8 + (lane & 7);
    const int lchA  = (lane >> 4) & 1;           // k-chunk select for A mats
    const int lrowB = ((lane >> 4) & 1) * 8 + (lane & 7);
    const int lchB  = (lane >> 3) & 1;           // k-chunk select for B mats

    const uint32_t smem_b = (uint32_t)__cvta_generic_to_shared(sm);

    float acc[4][4][4];
#pragma unroll
    for (int i = 0; i < 4; i++)
#pragma unroll
        for (int j = 0; j < 4; j++)
#pragma unroll
            for (int v = 0; v < 4; v++) acc[i][j][v] = 0.f;

    auto issue = [&](int slab, int stage) {
        int k0 = slab * KT;
        uint32_t* base = sm + stage * 4 * PLANE;
#pragma unroll
        for (int i = 0; i < 2; i++) {
            int f = tid + i * 256;
            int m = f >> 2, cc = f & 3;
            size_t ga = (size_t)(bm + m) * K + k0 + cc * 8;
            size_t gb = (size_t)(bn + m) * K + k0 + cc * 8;
            int off = m * STRIDE + cc * 4;
            cpasync16(base + 0 * PLANE + off, Ahi + ga);
            cpasync16(base + 1 * PLANE + off, Alo + ga);
            cpasync16(base + 2 * PLANE + off, Bhi + gb);
            cpasync16(base + 3 * PLANE + off, Blo + gb);
        }
        cp_commit();
    };

    auto compute = [&](int stage) {
        uint32_t Ahb = smem_b + (stage * 4 + 0) * PLANE * 4;
        uint32_t Alb = smem_b + (stage * 4 + 1) * PLANE * 4;
        uint32_t Bhb = smem_b + (stage * 4 + 2) * PLANE * 4;
        uint32_t Blb = smem_b + (stage * 4 + 3) * PLANE * 4;
        // byte offsets for this lane
        uint32_t aoff = (uint32_t)((wm * 64 + lrowA) * STRIDE + lchA * 4) * 4;
        uint32_t boff = (uint32_t)((wn * 32 + lrowB) * STRIDE + lchB * 4) * 4;
#pragma unroll
        for (int k16 = 0; k16 < 2; k16++) {
            uint32_t kb = (uint32_t)(k16 * 8) * 4;   // word offset 8 per k16
            uint32_t bh[4][2], bl[4][2];
#pragma unroll
            for (int p = 0; p < 2; p++) {
                uint32_t bo = boff + kb + (uint32_t)(p * 16 * STRIDE) * 4;
                uint32_t r4[4];
                ldsm4(r4, Bhb + bo);
                bh[p * 2][0] = r4[0]; bh[p * 2][1] = r4[1];
                bh[p * 2 + 1][0] = r4[2]; bh[p * 2 + 1][1] = r4[3];
                ldsm4(r4, Blb + bo);
                bl[p * 2][0] = r4[0]; bl[p * 2][1] = r4[1];
                bl[p * 2 + 1][0] = r4[2]; bl[p * 2 + 1][1] = r4[3];
            }
#pragma unroll
            for (int mi = 0; mi < 4; mi++) {
                uint32_t ao = aoff + kb + (uint32_t)(mi * 16 * STRIDE) * 4;
                uint32_t ah[4], al[4];
                ldsm4(ah, Ahb + ao);
#pragma unroll
                for (int ni = 0; ni < 4; ni++) {
                    mma_bf16(acc[mi][ni], ah, bh[ni]);
                    mma_bf16(acc[mi][ni], ah, bl[ni]);
                }
                ldsm4(al, Alb + ao);
#pragma unroll
                for (int ni = 0; ni < 4; ni++)
                    mma_bf16(acc[mi][ni], al, bh[ni]);
            }
        }
    };

    if (NSLABS > 0) {
        issue(s0, 0);
        if (NSLABS > 1) issue(s0 + 1, 1); else cp_commit();
        for (int s = 0; s < NSLABS; s++) {
            if (s + 1 < NSLABS) asm volatile("cp.async.wait_group 1;\n");
            else                asm volatile("cp.async.wait_group 0;\n");
            __syncthreads();
            compute(s & 1);
            __syncthreads();
            if (s + 2 < NSLABS) issue(s0 + s + 2, s & 1);
        }
    }

    // ----------------- epilogue -----------------
#pragma unroll
    for (int mi = 0; mi < 4; mi++) {
#pragma unroll
        for (int ni = 0; ni < 4; ni++) {
            int m0 = bm + wm * 64 + mi * 16 + q;
            int n0 = bn + wn * 32 + ni * 8 + r * 2;
            float* a = acc[mi][ni];

            if (MODE == 1) {
                float bv0 = bias[n0], bv1 = bias[n0 + 1];
                float v00 = a[0] + bv0, v01 = a[1] + bv1;
                float v10 = a[2] + bv0, v11 = a[3] + bv1;
                bf16 h0, l0, h1, l1;
                split1(v00, h0, l0); split1(v01, h1, l1);
                *(__nv_bfloat162*)(Chi + (size_t)m0 * N + n0) = __nv_bfloat162(h0, h1);
                *(__nv_bfloat162*)(Clo + (size_t)m0 * N + n0) = __nv_bfloat162(l0, l1);
                split1(v10, h0, l0); split1(v11, h1, l1);
                *(__nv_bfloat162*)(Chi + (size_t)(m0 + 8) * N + n0) = __nv_bfloat162(h0, h1);
                *(__nv_bfloat162*)(Clo + (size_t)(m0 + 8) * N + n0) = __nv_bfloat162(l0, l1);
            } else if (MODE == 4) {
                float* dst = Cf + ((size_t)blockIdx.z * M + m0) * N + n0;
                dst[0] = a[0]; dst[1] = a[1];
                dst += (size_t)8 * N;
                dst[0] = a[2]; dst[1] = a[3];
            } else {
                bool cell = (MODE == 2) || (m0 < BB);
                float a0, a1, a2, a3;
                if (MODE == 2) {
                    float2 g0 = *(const float2*)(gx + (size_t)m0 * N + n0);
                    float2 g1 = *(const float2*)(gx + (size_t)(m0 + 8) * N + n0);
                    a0 = a[0] + g0.x; a1 = a[1] + g0.y;
                    a2 = a[2] + g1.x; a3 = a[3] + g1.y;
                } else {
                    float bv0 = bias[n0], bv1 = bias[n0 + 1];
                    a0 = a[0] + bv0; a1 = a[1] + bv1;
                    a2 = a[2] + bv0; a3 = a[3] + bv1;
                }
                if (cell) {
                    // lane pair (r even: i,f) / (r odd: g,o) for same n
                    float p0 = __shfl_xor_sync(0xFFFFFFFFu, a0, 1);
                    float p1 = __shfl_xor_sync(0xFFFFFFFFu, a1, 1);
                    float p2 = __shfl_xor_sync(0xFFFFFFFFu, a2, 1);
                    float p3 = __shfl_xor_sync(0xFFFFFFFFu, a3, 1);
                    if ((r & 1) == 0) {
                        int n = n0 >> 2;
#pragma unroll
                        for (int rr = 0; rr < 2; rr++) {
                            int m = m0 + rr * 8;
                            float gi = rr ? a2 : a0;
                            float gf = rr ? a3 : a1;
                            float gg = rr ? p2 : p0;
                            float go = rr ? p3 : p1;
                            int fz = (MODE == 3) ? 1 : first;
                            float cold = fz ? 0.f : cstate[(size_t)m * HH + n];
                            float cn = sigm(gf) * cold + sigm(gi) * tanhf(gg);
                            cstate[(size_t)m * HH + n] = cn;
                            float h = sigm(go) * tanhf(cn);
                            bf16 hh, hl;
                            split1(h, hh, hl);
                            Chi[(size_t)m * HH + n] = hh;
                            Clo[(size_t)m * HH + n] = hl;
                        }
                    }
                } else {
                    // MODE 3, t > 0 rows: gx = acc + bias
                    float* dst = Cf + (size_t)m0 * N + n0;
                    dst[0] = a0; dst[1] = a1;
                    dst += (size_t)8 * N;
                    dst[0] = a2; dst[1] = a3;
                }
            }
        }
    }
}

// ---------------- prep / reshape kernels -------------------------------------
__global__ void split_fcw(const float* __restrict__ w0, const float* __restrict__ w1,
                          bf16* __restrict__ h0, bf16* __restrict__ l0,
                          bf16* __restrict__ h1, bf16* __restrict__ l1)
{
    int i = blockIdx.x * blockDim.x + threadIdx.x;
    const int n0 = HH * HH;
    if (i < n0) split1(w0[i], h0[i], l0[i]);
    else if (i < n0 + HH * KFC1) { int j = i - n0; split1(w1[j], h1[j], l1[j]); }
}

// row j = n*4+g  <-  row g*HH+n  (per layer), both wih & whh
__global__ void permute_both(const float* __restrict__ wih, const float* __restrict__ whh,
                             bf16* __restrict__ ihh, bf16* __restrict__ ihl,
                             bf16* __restrict__ hhh, bf16* __restrict__ hhl)
{
    int i = blockIdx.x * blockDim.x + threadIdx.x;
    const int per = LAYERS * G4H * HH;
    if (i >= 2 * per) return;
    int sel = i >= per;
    int ii = sel ? i - per : i;
    int k = ii % HH;
    int j = (ii / HH) % G4H;
    int l = ii / (HH * G4H);
    int n = j >> 2, g = j & 3;
    const float* src = sel ? whh : wih;
    float v = src[(size_t)l * G4H * HH + (size_t)(g * HH + n) * HH + k];
    if (sel) split1(v, hhh[ii], hhl[ii]);
    else     split1(v, ihh[ii], ihl[ii]);
}

__global__ void combine_bias(const float* __restrict__ bih,
                             const float* __restrict__ bhh, float* __restrict__ bc)
{
    int i = blockIdx.x * blockDim.x + threadIdx.x;
    if (i >= LAYERS * G4H) return;
    int j = i % G4H;
    int l = i / G4H;
    int n = j >> 2, g = j & 3;
    bc[i] = bih[l * G4H + g * HH + n] + bhh[l * G4H + g * HH + n];
}

// (B,W,H) fp32 -> (W*B, H) split bf16
__global__ void transpose_split(const float* __restrict__ src,
                                bf16* __restrict__ hi, bf16* __restrict__ lo)
{
    int i = blockIdx.x * blockDim.x + threadIdx.x;
    if (i >= TB * HH) return;
    int k = i % HH;
    int row = i / HH;
    int t = row / BB, b = row % BB;
    split1(src[((size_t)b * WW + t) * HH + k], hi[i], lo[i]);
}

// (W,B,H) split -> (B, W*H) split
__global__ void pack_split(const bf16* __restrict__ xhi, const bf16* __restrict__ xlo,
                           bf16* __restrict__ chi, bf16* __restrict__ clo)
{
    int i = blockIdx.x * blockDim.x + threadIdx.x;
    if (i >= BB * KFC1) return;
    int b = i / KFC1;
    int tk = i % KFC1;
    int t = tk / HH, k = tk % HH;
    size_t s = ((size_t)t * BB + b) * HH + k;
    chi[i] = xhi[s];
    clo[i] = xlo[s];
}

__global__ void reduce_fc1(const float* __restrict__ part, const float* __restrict__ b,
                           float* __restrict__ out)
{
    int i = blockIdx.x * blockDim.x + threadIdx.x;
    if (i >= BB * HH) return;
    float s = b[i % HH];
#pragma unroll
    for (int z = 0; z < SPLITK; z++) s += part[(size_t)z * BB * HH + i];
    out[i] = s;
}

// ---------------- host -------------------------------------------------------
extern "C" void kernel_launch(void* const* d_in, const int* in_sizes, int n_in,
                              void* d_out, int out_size)
{
    const float* xpos  = (const float*)d_in[0];
    const float* fc0_w = (const float*)d_in[1];
    const float* fc0_b = (const float*)d_in[2];
    const float* w_ih  = (const float*)d_in[3];
    const float* w_hh  = (const float*)d_in[4];
    const float* b_ih  = (const float*)d_in[5];
    const float* b_hh  = (const float*)d_in[6];
    const float* fc1_w = (const float*)d_in[7];
    const float* fc1_b = (const float*)d_in[8];
    float* out = (float*)d_out;

    bf16 *xAhi, *xAlo, *xBhi, *xBlo, *xcathi, *xcatlo;
    bf16 *fc0whi, *fc0wlo, *fc1whi, *fc1wlo, *wihhi, *wihlo, *whhhi, *whhlo;
    float *gx, *c, *bcomb, *part;
    cudaGetSymbolAddress((void**)&xAhi, g_xAhi);
    cudaGetSymbolAddress((void**)&xAlo, g_xAlo);
    cudaGetSymbolAddress((void**)&xBhi, g_xBhi);
    cudaGetSymbolAddress((void**)&xBlo, g_xBlo);
    cudaGetSymbolAddress((void**)&xcathi, g_xcathi);
    cudaGetSymbolAddress((void**)&xcatlo, g_xcatlo);
    cudaGetSymbolAddress((void**)&fc0whi, g_fc0whi);
    cudaGetSymbolAddress((void**)&fc0wlo, g_fc0wlo);
    cudaGetSymbolAddress((void**)&fc1whi, g_fc1whi);
    cudaGetSymbolAddress((void**)&fc1wlo, g_fc1wlo);
    cudaGetSymbolAddress((void**)&wihhi, g_wihhi);
    cudaGetSymbolAddress((void**)&wihlo, g_wihlo);
    cudaGetSymbolAddress((void**)&whhhi, g_whhhi);
    cudaGetSymbolAddress((void**)&whhlo, g_whhlo);
    cudaGetSymbolAddress((void**)&gx,    g_gx);
    cudaGetSymbolAddress((void**)&c,     g_c);
    cudaGetSymbolAddress((void**)&bcomb, g_bcomb);
    cudaGetSymbolAddress((void**)&part,  g_part);

    static bool once = false;
    if (!once) {
        cudaFuncSetAttribute(gemm_bf16<1>, cudaFuncAttributeMaxDynamicSharedMemorySize, SMEM_BYTES);
        cudaFuncSetAttribute(gemm_bf16<2>, cudaFuncAttributeMaxDynamicSharedMemorySize, SMEM_BYTES);
        cudaFuncSetAttribute(gemm_bf16<3>, cudaFuncAttributeMaxDynamicSharedMemorySize, SMEM_BYTES);
        cudaFuncSetAttribute(gemm_bf16<4>, cudaFuncAttributeMaxDynamicSharedMemorySize, SMEM_BYTES);
        once = true;
    }

    const int EL = 256;

    // prep: launches 1-4, so ncu (-s 5 -c 1) lands on a GEMM
    {
        int n = HH * HH + HH * KFC1;
        split_fcw<<<(n + EL - 1) / EL, EL>>>(fc0_w, fc1_w, fc0whi, fc0wlo, fc1whi, fc1wlo);
    }
    {
        int n = 2 * LAYERS * G4H * HH;
        permute_both<<<(n + EL - 1) / EL, EL>>>(w_ih, w_hh, wihhi, wihlo, whhhi, whhlo);
    }
    combine_bias<<<(LAYERS * G4H + EL - 1) / EL, EL>>>(b_ih, b_hh, bcomb);
    transpose_split<<<(TB * HH + EL - 1) / EL, EL>>>(xpos, xcathi, xcatlo);

    // fc0: xA = xin @ fc0_w^T + b (split store)
    gemm_bf16<1><<<dim3(HH / 128, TB / 128, 1), 256, SMEM_BYTES>>>(
        xcathi, xcatlo, fc0whi, fc0wlo, fc0_b,
        nullptr, xAhi, xAlo, nullptr, nullptr, 0, TB, HH, HH, 1);

    for (int l = 0; l < LAYERS; l++) {
        bf16* ih = (l & 1) ? xBhi : xAhi;
        bf16* il = (l & 1) ? xBlo : xAlo;
        bf16* oh = (l & 1) ? xAhi : xBhi;
        bf16* ol = (l & 1) ? xAlo : xBlo;
        const bf16* wihh = wihhi + (size_t)l * G4H * HH;
        const bf16* wihl = wihlo + (size_t)l * G4H * HH;
        const bf16* whhh = whhhi + (size_t)l * G4H * HH;
        const bf16* whhl = whhlo + (size_t)l * G4H * HH;
        const float* bl_ = bcomb + (size_t)l * G4H;

        // input GEMM: t=0 rows -> fused cell into oh/ol; t>0 rows -> gx (+bias)
        gemm_bf16<3><<<dim3(G4H / 128, TB / 128, 1), 256, SMEM_BYTES>>>(
            ih, il, wihh, wihl, bl_,
            gx, oh, ol, nullptr, c, 1, TB, G4H, HH, 1);

        for (int t = 1; t < WW; t++) {
            gemm_bf16<2><<<dim3(G4H / 128, BB / 128, 1), 256, SMEM_BYTES>>>(
                oh + (size_t)(t - 1) * BB * HH, ol + (size_t)(t - 1) * BB * HH,
                whhh, whhl, nullptr,
                nullptr, oh + (size_t)t * BB * HH, ol + (size_t)t * BB * HH,
                gx + (size_t)t * BB * G4H, c, 0, BB, G4H, HH, 1);
        }
    }

    // final activations in xA (10 layers, even count)
    pack_split<<<(BB * KFC1 + EL - 1) / EL, EL>>>(xAhi, xAlo, xcathi, xcatlo);

    // fc1 split-K partials + reduce
    gemm_bf16<4><<<dim3(HH / 128, BB / 128, SPLITK), 256, SMEM_BYTES>>>(
        xcathi, xcatlo, fc1whi, fc1wlo, nullptr,
        part, nullptr, nullptr, nullptr, nullptr, 0, BB, HH, KFC1, SPLITK);
    reduce_fc1<<<(BB * HH + EL - 1) / EL, EL>>>(part, fc1_b, out);
}

// round 10
// speedup vs baseline: 3.0231x; 1.0292x over previous
#include <cuda_runtime.h>
#include <cuda_bf16.h>
#include <math.h>
#include <stdint.h>

#define HH 768
#define LAYERS 10
#define WW 10
#define BB 512
#define G4H 3072
#define TB 5120          // WW*BB
#define KFC1 (WW*HH)     // 7680
#define SPLITK 12

#define KT 32          // K-slab in elements
#define STRIDE 20      // u32 per smem row (16 used + 4 pad; ldmatrix conflict-free)
#define PLANE (128 * STRIDE)           // u32 per plane
#define SMEM_BYTES (2 * 4 * PLANE * 4)     // 81920  (2-stage, regular GEMM)
#define RSMEM_BYTES (4 * 4 * PLANE * 4)    // 163840 (4-stage, persistent)

typedef __nv_bfloat16 bf16;

// ---------------- scratch (device globals; allocation-free rule) -------------
__device__ bf16  g_xAhi[TB * HH], g_xAlo[TB * HH];
__device__ bf16  g_xBhi[TB * HH], g_xBlo[TB * HH];
__device__ float g_gx[TB * G4H];
__device__ float g_c[BB * HH];
__device__ bf16  g_xcathi[BB * KFC1], g_xcatlo[BB * KFC1];   // also fc0 input temp
__device__ bf16  g_fc0whi[HH * HH],   g_fc0wlo[HH * HH];
__device__ bf16  g_fc1whi[HH * KFC1], g_fc1wlo[HH * KFC1];
__device__ bf16  g_wihhi[LAYERS * G4H * HH], g_wihlo[LAYERS * G4H * HH];
__device__ bf16  g_whhhi[LAYERS * G4H * HH], g_whhlo[LAYERS * G4H * HH];
__device__ float g_bcomb[LAYERS * G4H];
__device__ float g_part[SPLITK * BB * HH];
__device__ int   g_ctr[LAYERS * 8];          // grid barriers (reset every call)

// ---------------- helpers ----------------------------------------------------
__device__ __forceinline__ void split1(float v, bf16& h, bf16& l)
{
    h = __float2bfloat16_rn(v);
    l = __float2bfloat16_rn(v - __bfloat162float(h));
}

__device__ __forceinline__ float sigm(float x) { return 1.0f / (1.0f + expf(-x)); }

__device__ __forceinline__ void cpasync16(void* dst, const void* src)
{
    uint32_t s = (uint32_t)__cvta_generic_to_shared(dst);
    asm volatile("cp.async.cg.shared.global [%0], [%1], 16;\n" :: "r"(s), "l"(src));
}
__device__ __forceinline__ void cp_commit() { asm volatile("cp.async.commit_group;\n"); }

__device__ __forceinline__ void mma_bf16(float* c, const uint32_t* a, const uint32_t* b)
{
    asm volatile(
        "mma.sync.aligned.m16n8k16.row.col.f32.bf16.bf16.f32 "
        "{%0,%1,%2,%3}, {%4,%5,%6,%7}, {%8,%9}, {%0,%1,%2,%3};"
        : "+f"(c[0]), "+f"(c[1]), "+f"(c[2]), "+f"(c[3])
        : "r"(a[0]), "r"(a[1]), "r"(a[2]), "r"(a[3]), "r"(b[0]), "r"(b[1]));
}

__device__ __forceinline__ void ldsm4(uint32_t* r, uint32_t saddr)
{
    asm volatile("ldmatrix.sync.aligned.m8n8.x4.shared.b16 {%0,%1,%2,%3}, [%4];"
                 : "=r"(r[0]), "=r"(r[1]), "=r"(r[2]), "=r"(r[3]) : "r"(saddr));
}

// ---------------- regular GEMM (2-stage, occ 2) ------------------------------
// MODE 1: (Chi,Clo) split bf16 = acc + bias                       (fc0)
// MODE 3: rows<BB fused cell first=1 (g = acc + bias); rows>=BB: gx = acc + bias
// MODE 4: raw fp32 partial store (split-K via blockIdx.z)         (fc1)
template <int MODE>
__global__ __launch_bounds__(256, 2) void gemm_bf16(
    const bf16* __restrict__ Ahi, const bf16* __restrict__ Alo,
    const bf16* __restrict__ Bhi, const bf16* __restrict__ Blo,
    const float* __restrict__ bias,
    float* __restrict__ Cf,
    bf16* __restrict__ Chi, bf16* __restrict__ Clo,
    float* __restrict__ cstate,
    int M, int N, int K, int nsplit)
{
    extern __shared__ uint32_t sm[];
    const int tid = threadIdx.x;
    const int lane = tid & 31;
    const int wid = tid >> 5;
    const int wm = wid >> 2;          // 0..1
    const int wn = wid & 3;           // 0..3
    const int bm = blockIdx.y * 128;
    const int bn = blockIdx.x * 128;
    const int q = lane >> 2;
    const int r = lane & 3;

    const int NS = K / KT;
    const int NSLABS = NS / nsplit;
    const int s0 = blockIdx.z * NSLABS;

    const int lrowA = ((lane >> 3) & 1) * 8 + (lane & 7);
    const int lchA  = (lane >> 4) & 1;
    const int lrowB = ((lane >> 4) & 1) * 8 + (lane & 7);
    const int lchB  = (lane >> 3) & 1;
    const uint32_t smem_b = (uint32_t)__cvta_generic_to_shared(sm);

    float acc[4][4][4];
#pragma unroll
    for (int i = 0; i < 4; i++)
#pragma unroll
        for (int j = 0; j < 4; j++)
#pragma unroll
            for (int v = 0; v < 4; v++) acc[i][j][v] = 0.f;

    auto issue = [&](int slab, int stage) {
        int k0 = slab * KT;
        uint32_t* base = sm + stage * 4 * PLANE;
#pragma unroll
        for (int i = 0; i < 2; i++) {
            int f = tid + i * 256;
            int m = f >> 2, cc = f & 3;
            size_t ga = (size_t)(bm + m) * K + k0 + cc * 8;
            size_t gb = (size_t)(bn + m) * K + k0 + cc * 8;
            int off = m * STRIDE + cc * 4;
            cpasync16(base + 0 * PLANE + off, Ahi + ga);
            cpasync16(base + 1 * PLANE + off, Alo + ga);
            cpasync16(base + 2 * PLANE + off, Bhi + gb);
            cpasync16(base + 3 * PLANE + off, Blo + gb);
        }
        cp_commit();
    };

    auto compute = [&](int stage) {
        uint32_t Ahb = smem_b + (stage * 4 + 0) * PLANE * 4;
        uint32_t Alb = smem_b + (stage * 4 + 1) * PLANE * 4;
        uint32_t Bhb = smem_b + (stage * 4 + 2) * PLANE * 4;
        uint32_t Blb = smem_b + (stage * 4 + 3) * PLANE * 4;
        uint32_t aoff = (uint32_t)((wm * 64 + lrowA) * STRIDE + lchA * 4) * 4;
        uint32_t boff = (uint32_t)((wn * 32 + lrowB) * STRIDE + lchB * 4) * 4;
#pragma unroll
        for (int k16 = 0; k16 < 2; k16++) {
            uint32_t kb = (uint32_t)(k16 * 8) * 4;
            uint32_t bh[4][2], bl[4][2];
#pragma unroll
            for (int p = 0; p < 2; p++) {
                uint32_t bo = boff + kb + (uint32_t)(p * 16 * STRIDE) * 4;
                uint32_t r4[4];
                ldsm4(r4, Bhb + bo);
                bh[p * 2][0] = r4[0]; bh[p * 2][1] = r4[1];
                bh[p * 2 + 1][0] = r4[2]; bh[p * 2 + 1][1] = r4[3];
                ldsm4(r4, Blb + bo);
                bl[p * 2][0] = r4[0]; bl[p * 2][1] = r4[1];
                bl[p * 2 + 1][0] = r4[2]; bl[p * 2 + 1][1] = r4[3];
            }
#pragma unroll
            for (int mi = 0; mi < 4; mi++) {
                uint32_t ao = aoff + kb + (uint32_t)(mi * 16 * STRIDE) * 4;
                uint32_t ah[4], al[4];
                ldsm4(ah, Ahb + ao);
#pragma unroll
                for (int ni = 0; ni < 4; ni++) {
                    mma_bf16(acc[mi][ni], ah, bh[ni]);
                    mma_bf16(acc[mi][ni], ah, bl[ni]);
                }
                ldsm4(al, Alb + ao);
#pragma unroll
                for (int ni = 0; ni < 4; ni++)
                    mma_bf16(acc[mi][ni], al, bh[ni]);
            }
        }
    };

    issue(s0, 0);
    if (NSLABS > 1) issue(s0 + 1, 1); else cp_commit();
    for (int s = 0; s < NSLABS; s++) {
        if (s + 1 < NSLABS) asm volatile("cp.async.wait_group 1;\n");
        else                asm volatile("cp.async.wait_group 0;\n");
        __syncthreads();
        compute(s & 1);
        __syncthreads();
        if (s + 2 < NSLABS) issue(s0 + s + 2, s & 1);
    }

    // ----------------- epilogue -----------------
#pragma unroll
    for (int mi = 0; mi < 4; mi++) {
#pragma unroll
        for (int ni = 0; ni < 4; ni++) {
            int m0 = bm + wm * 64 + mi * 16 + q;
            int n0 = bn + wn * 32 + ni * 8 + r * 2;
            float* a = acc[mi][ni];

            if (MODE == 1) {
                float bv0 = bias[n0], bv1 = bias[n0 + 1];
                float v00 = a[0] + bv0, v01 = a[1] + bv1;
                float v10 = a[2] + bv0, v11 = a[3] + bv1;
                bf16 h0, l0, h1, l1;
                split1(v00, h0, l0); split1(v01, h1, l1);
                *(__nv_bfloat162*)(Chi + (size_t)m0 * N + n0) = __nv_bfloat162(h0, h1);
                *(__nv_bfloat162*)(Clo + (size_t)m0 * N + n0) = __nv_bfloat162(l0, l1);
                split1(v10, h0, l0); split1(v11, h1, l1);
                *(__nv_bfloat162*)(Chi + (size_t)(m0 + 8) * N + n0) = __nv_bfloat162(h0, h1);
                *(__nv_bfloat162*)(Clo + (size_t)(m0 + 8) * N + n0) = __nv_bfloat162(l0, l1);
            } else if (MODE == 4) {
                float* dst = Cf + ((size_t)blockIdx.z * M + m0) * N + n0;
                dst[0] = a[0]; dst[1] = a[1];
                dst += (size_t)8 * N;
                dst[0] = a[2]; dst[1] = a[3];
            } else {
                float bv0 = bias[n0], bv1 = bias[n0 + 1];
                float a0 = a[0] + bv0, a1 = a[1] + bv1;
                float a2 = a[2] + bv0, a3 = a[3] + bv1;
                if (m0 < BB) {
                    // fused t=0 cell
                    float p0 = __shfl_xor_sync(0xFFFFFFFFu, a0, 1);
                    float p1 = __shfl_xor_sync(0xFFFFFFFFu, a1, 1);
                    float p2 = __shfl_xor_sync(0xFFFFFFFFu, a2, 1);
                    float p3 = __shfl_xor_sync(0xFFFFFFFFu, a3, 1);
                    if ((r & 1) == 0) {
                        int n = n0 >> 2;
#pragma unroll
                        for (int rr = 0; rr < 2; rr++) {
                            int m = m0 + rr * 8;
                            float gi = rr ? a2 : a0;
                            float gf = rr ? a3 : a1;
                            float gg = rr ? p2 : p0;
                            float go = rr ? p3 : p1;
                            (void)gf;
                            float cn = sigm(gi) * tanhf(gg);
                            cstate[(size_t)m * HH + n] = cn;
                            float h = sigm(go) * tanhf(cn);
                            bf16 hh, hl;
                            split1(h, hh, hl);
                            Chi[(size_t)m * HH + n] = hh;
                            Clo[(size_t)m * HH + n] = hl;
                        }
                    }
                } else {
                    float* dst = Cf + (size_t)m0 * N + n0;
                    dst[0] = a0; dst[1] = a1;
                    dst += (size_t)8 * N;
                    dst[0] = a2; dst[1] = a3;
                }
            }
        }
    }
}

// ---------------- persistent recurrent layer (grid 96, occ 1, 4-stage) -------
__global__ __launch_bounds__(256, 1) void rec_layer(
    bf16* __restrict__ oh, bf16* __restrict__ ol,
    const bf16* __restrict__ Bhi, const bf16* __restrict__ Blo,
    const float* __restrict__ gx, float* __restrict__ cstate,
    int* __restrict__ ctr)
{
    extern __shared__ uint32_t sm[];
    const int tid = threadIdx.x;
    const int lane = tid & 31;
    const int wid = tid >> 5;
    const int wm = wid >> 2;
    const int wn = wid & 3;
    const int bm = blockIdx.y * 128;
    const int bn = blockIdx.x * 128;
    const int q = lane >> 2;
    const int r = lane & 3;

    const int lrowA = ((lane >> 3) & 1) * 8 + (lane & 7);
    const int lchA  = (lane >> 4) & 1;
    const int lrowB = ((lane >> 4) & 1) * 8 + (lane & 7);
    const int lchB  = (lane >> 3) & 1;
    const uint32_t smem_b = (uint32_t)__cvta_generic_to_shared(sm);

    for (int t = 1; t < WW; t++) {
        const bf16* Ahi = (const bf16*)(oh + (size_t)(t - 1) * BB * HH);
        const bf16* Alo = (const bf16*)(ol + (size_t)(t - 1) * BB * HH);

        float acc[4][4][4];
#pragma unroll
        for (int i = 0; i < 4; i++)
#pragma unroll
            for (int j = 0; j < 4; j++)
#pragma unroll
                for (int v = 0; v < 4; v++) acc[i][j][v] = 0.f;

        auto issue = [&](int slab, int stage) {
            int k0 = slab * KT;
            uint32_t* base = sm + stage * 4 * PLANE;
#pragma unroll
            for (int i = 0; i < 2; i++) {
                int f = tid + i * 256;
                int m = f >> 2, cc = f & 3;
                size_t ga = (size_t)(bm + m) * HH + k0 + cc * 8;
                size_t gb = (size_t)(bn + m) * HH + k0 + cc * 8;
                int off = m * STRIDE + cc * 4;
                cpasync16(base + 0 * PLANE + off, Ahi + ga);
                cpasync16(base + 1 * PLANE + off, Alo + ga);
                cpasync16(base + 2 * PLANE + off, Bhi + gb);
                cpasync16(base + 3 * PLANE + off, Blo + gb);
            }
            cp_commit();
        };

        auto compute = [&](int stage) {
            uint32_t Ahb = smem_b + (stage * 4 + 0) * PLANE * 4;
            uint32_t Alb = smem_b + (stage * 4 + 1) * PLANE * 4;
            uint32_t Bhb = smem_b + (stage * 4 + 2) * PLANE * 4;
            uint32_t Blb = smem_b + (stage * 4 + 3) * PLANE * 4;
            uint32_t aoff = (uint32_t)((wm * 64 + lrowA) * STRIDE + lchA * 4) * 4;
            uint32_t boff = (uint32_t)((wn * 32 + lrowB) * STRIDE + lchB * 4) * 4;
#pragma unroll
            for (int k16 = 0; k16 < 2; k16++) {
                uint32_t kb = (uint32_t)(k16 * 8) * 4;
                uint32_t bh[4][2], bl[4][2];
#pragma unroll
                for (int p = 0; p < 2; p++) {
                    uint32_t bo = boff + kb + (uint32_t)(p * 16 * STRIDE) * 4;
                    uint32_t r4[4];
                    ldsm4(r4, Bhb + bo);
                    bh[p * 2][0] = r4[0]; bh[p * 2][1] = r4[1];
                    bh[p * 2 + 1][0] = r4[2]; bh[p * 2 + 1][1] = r4[3];
                    ldsm4(r4, Blb + bo);
                    bl[p * 2][0] = r4[0]; bl[p * 2][1] = r4[1];
                    bl[p * 2 + 1][0] = r4[2]; bl[p * 2 + 1][1] = r4[3];
                }
#pragma unroll
                for (int mi = 0; mi < 4; mi++) {
                    uint32_t ao = aoff + kb + (uint32_t)(mi * 16 * STRIDE) * 4;
                    uint32_t ah[4], al[4];
                    ldsm4(ah, Ahb + ao);
#pragma unroll
                    for (int ni = 0; ni < 4; ni++) {
                        mma_bf16(acc[mi][ni], ah, bh[ni]);
                        mma_bf16(acc[mi][ni], ah, bl[ni]);
                    }
                    ldsm4(al, Alb + ao);
#pragma unroll
                    for (int ni = 0; ni < 4; ni++)
                        mma_bf16(acc[mi][ni], al, bh[ni]);
                }
            }
        };

        issue(0, 0); issue(1, 1); issue(2, 2);
        for (int s = 0; s < 24; s++) {
            if (s >= 23)      asm volatile("cp.async.wait_group 0;\n");
            else if (s >= 22) asm volatile("cp.async.wait_group 1;\n");
            else              asm volatile("cp.async.wait_group 2;\n");
            __syncthreads();
            compute(s & 3);
            if (s + 3 < 24) issue(s + 3, (s + 3) & 3);
        }

        // epilogue: fused LSTM cell
        const float* gxt = gx + (size_t)t * BB * G4H;
        bf16* Chi = oh + (size_t)t * BB * HH;
        bf16* Clo = ol + (size_t)t * BB * HH;
#pragma unroll
        for (int mi = 0; mi < 4; mi++) {
#pragma unroll
            for (int ni = 0; ni < 4; ni++) {
                int m0 = bm + wm * 64 + mi * 16 + q;
                int n0 = bn + wn * 32 + ni * 8 + r * 2;
                float* a = acc[mi][ni];
                float2 g0 = *(const float2*)(gxt + (size_t)m0 * G4H + n0);
                float2 g1 = *(const float2*)(gxt + (size_t)(m0 + 8) * G4H + n0);
                float a0 = a[0] + g0.x, a1 = a[1] + g0.y;
                float a2 = a[2] + g1.x, a3 = a[3] + g1.y;
                float p0 = __shfl_xor_sync(0xFFFFFFFFu, a0, 1);
                float p1 = __shfl_xor_sync(0xFFFFFFFFu, a1, 1);
                float p2 = __shfl_xor_sync(0xFFFFFFFFu, a2, 1);
                float p3 = __shfl_xor_sync(0xFFFFFFFFu, a3, 1);
                if ((r & 1) == 0) {
                    int n = n0 >> 2;
#pragma unroll
                    for (int rr = 0; rr < 2; rr++) {
                        int m = m0 + rr * 8;
                        float gi = rr ? a2 : a0;
                        float gf = rr ? a3 : a1;
                        float gg = rr ? p2 : p0;
                        float go = rr ? p3 : p1;
                        float cold = cstate[(size_t)m * HH + n];
                        float cn = sigm(gf) * cold + sigm(gi) * tanhf(gg);
                        cstate[(size_t)m * HH + n] = cn;
                        float h = sigm(go) * tanhf(cn);
                        bf16 hh, hl;
                        split1(h, hh, hl);
                        Chi[(size_t)m * HH + n] = hh;
                        Clo[(size_t)m * HH + n] = hl;
                    }
                }
            }
        }

        // grid barrier (h(t) must be visible before any CTA starts step t+1)
        if (t < WW - 1) {
            __threadfence();
            __syncthreads();
            if (tid == 0) {
                atomicAdd(&ctr[t - 1], 1);
                while (atomicAdd(&ctr[t - 1], 0) < 96) __nanosleep(128);
            }
            __syncthreads();
        }
    }
}

// ---------------- prep (merged): weight splits + permute + bias + ctr reset --
__global__ void prep_all(const float* __restrict__ fc0_w, const float* __restrict__ fc1_w,
                         const float* __restrict__ wih, const float* __restrict__ whh,
                         const float* __restrict__ bih, const float* __restrict__ bhh,
                         bf16* __restrict__ f0h, bf16* __restrict__ f0l,
                         bf16* __restrict__ f1h, bf16* __restrict__ f1l,
                         bf16* __restrict__ ihh, bf16* __restrict__ ihl,
                         bf16* __restrict__ hhh, bf16* __restrict__ hhl,
                         float* __restrict__ bc, int* __restrict__ ctr)
{
    int i = blockIdx.x * blockDim.x + threadIdx.x;
    const int NA = HH * HH;
    const int NB = NA + HH * KFC1;
    const int NP = 2 * LAYERS * G4H * HH;
    if (i < NA) { split1(fc0_w[i], f0h[i], f0l[i]); return; }
    if (i < NB) { int j = i - NA; split1(fc1_w[j], f1h[j], f1l[j]); return; }
    int i2 = i - NB;
    if (i2 < NP) {
        int sel = i2 >= NP / 2;
        int ii = sel ? i2 - NP / 2 : i2;
        int k = ii % HH;
        int j = (ii / HH) % G4H;
        int l = ii / (HH * G4H);
        int n = j >> 2, g = j & 3;
        const float* src = sel ? whh : wih;
        float v = src[(size_t)l * G4H * HH + (size_t)(g * HH + n) * HH + k];
        if (sel) split1(v, hhh[ii], hhl[ii]);
        else     split1(v, ihh[ii], ihl[ii]);
        return;
    }
    int i3 = i2 - NP;
    if (i3 < LAYERS * G4H) {
        int j = i3 % G4H;
        int l = i3 / G4H;
        int n = j >> 2, g = j & 3;
        bc[i3] = bih[l * G4H + g * HH + n] + bhh[l * G4H + g * HH + n];
        return;
    }
    int i4 = i3 - LAYERS * G4H;
    if (i4 < LAYERS * 8) ctr[i4] = 0;
}

// (B,W,H) fp32 -> (W*B, H) split bf16
__global__ void transpose_split(const float* __restrict__ src,
                                bf16* __restrict__ hi, bf16* __restrict__ lo)
{
    int i = blockIdx.x * blockDim.x + threadIdx.x;
    if (i >= TB * HH) return;
    int k = i % HH;
    int row = i / HH;
    int t = row / BB, b = row % BB;
    split1(src[((size_t)b * WW + t) * HH + k], hi[i], lo[i]);
}

// (W,B,H) split -> (B, W*H) split
__global__ void pack_split(const bf16* __restrict__ xhi, const bf16* __restrict__ xlo,
                           bf16* __restrict__ chi, bf16* __restrict__ clo)
{
    int i = blockIdx.x * blockDim.x + threadIdx.x;
    if (i >= BB * KFC1) return;
    int b = i / KFC1;
    int tk = i % KFC1;
    int t = tk / HH, k = tk % HH;
    size_t s = ((size_t)t * BB + b) * HH + k;
    chi[i] = xhi[s];
    clo[i] = xlo[s];
}

__global__ void reduce_fc1(const float* __restrict__ part, const float* __restrict__ b,
                           float* __restrict__ out)
{
    int i = blockIdx.x * blockDim.x + threadIdx.x;
    if (i >= BB * HH) return;
    float s = b[i % HH];
#pragma unroll
    for (int z = 0; z < SPLITK; z++) s += part[(size_t)z * BB * HH + i];
    out[i] = s;
}

// ---------------- host -------------------------------------------------------
extern "C" void kernel_launch(void* const* d_in, const int* in_sizes, int n_in,
                              void* d_out, int out_size)
{
    const float* xpos  = (const float*)d_in[0];
    const float* fc0_w = (const float*)d_in[1];
    const float* fc0_b = (const float*)d_in[2];
    const float* w_ih  = (const float*)d_in[3];
    const float* w_hh  = (const float*)d_in[4];
    const float* b_ih  = (const float*)d_in[5];
    const float* b_hh  = (const float*)d_in[6];
    const float* fc1_w = (const float*)d_in[7];
    const float* fc1_b = (const float*)d_in[8];
    float* out = (float*)d_out;

    bf16 *xAhi, *xAlo, *xBhi, *xBlo, *xcathi, *xcatlo;
    bf16 *fc0whi, *fc0wlo, *fc1whi, *fc1wlo, *wihhi, *wihlo, *whhhi, *whhlo;
    float *gx, *c, *bcomb, *part;
    int* ctr;
    cudaGetSymbolAddress((void**)&xAhi, g_xAhi);
    cudaGetSymbolAddress((void**)&xAlo, g_xAlo);
    cudaGetSymbolAddress((void**)&xBhi, g_xBhi);
    cudaGetSymbolAddress((void**)&xBlo, g_xBlo);
    cudaGetSymbolAddress((void**)&xcathi, g_xcathi);
    cudaGetSymbolAddress((void**)&xcatlo, g_xcatlo);
    cudaGetSymbolAddress((void**)&fc0whi, g_fc0whi);
    cudaGetSymbolAddress((void**)&fc0wlo, g_fc0wlo);
    cudaGetSymbolAddress((void**)&fc1whi, g_fc1whi);
    cudaGetSymbolAddress((void**)&fc1wlo, g_fc1wlo);
    cudaGetSymbolAddress((void**)&wihhi, g_wihhi);
    cudaGetSymbolAddress((void**)&wihlo, g_wihlo);
    cudaGetSymbolAddress((void**)&whhhi, g_whhhi);
    cudaGetSymbolAddress((void**)&whhlo, g_whhlo);
    cudaGetSymbolAddress((void**)&gx,    g_gx);
    cudaGetSymbolAddress((void**)&c,     g_c);
    cudaGetSymbolAddress((void**)&bcomb, g_bcomb);
    cudaGetSymbolAddress((void**)&part,  g_part);
    cudaGetSymbolAddress((void**)&ctr,   g_ctr);

    static bool once = false;
    if (!once) {
        cudaFuncSetAttribute(gemm_bf16<1>, cudaFuncAttributeMaxDynamicSharedMemorySize, SMEM_BYTES);
        cudaFuncSetAttribute(gemm_bf16<3>, cudaFuncAttributeMaxDynamicSharedMemorySize, SMEM_BYTES);
        cudaFuncSetAttribute(gemm_bf16<4>, cudaFuncAttributeMaxDynamicSharedMemorySize, SMEM_BYTES);
        cudaFuncSetAttribute(rec_layer,    cudaFuncAttributeMaxDynamicSharedMemorySize, RSMEM_BYTES);
        once = true;
    }

    const int EL = 256;

    // launch 0: input transpose/split
    transpose_split<<<(TB * HH + EL - 1) / EL, EL>>>(xpos, xcathi, xcatlo);

    // launch 1: merged prep (weights, biases, barrier-counter reset)
    {
        int n = HH * HH + HH * KFC1 + 2 * LAYERS * G4H * HH + LAYERS * G4H + LAYERS * 8;
        prep_all<<<(n + EL - 1) / EL, EL>>>(fc0_w, fc1_w, w_ih, w_hh, b_ih, b_hh,
                                            fc0whi, fc0wlo, fc1whi, fc1wlo,
                                            wihhi, wihlo, whhhi, whhlo, bcomb, ctr);
    }

    // launch 2: fc0 (split store)
    gemm_bf16<1><<<dim3(HH / 128, TB / 128, 1), 256, SMEM_BYTES>>>(
        xcathi, xcatlo, fc0whi, fc0wlo, fc0_b,
        nullptr, xAhi, xAlo, nullptr, TB, HH, HH, 1);

    for (int l = 0; l < LAYERS; l++) {
        bf16* ih = (l & 1) ? xBhi : xAhi;
        bf16* il = (l & 1) ? xBlo : xAlo;
        bf16* oh = (l & 1) ? xAhi : xBhi;
        bf16* ol = (l & 1) ? xAlo : xBlo;
        const bf16* wihh = wihhi + (size_t)l * G4H * HH;
        const bf16* wihl = wihlo + (size_t)l * G4H * HH;
        const bf16* whhh = whhhi + (size_t)l * G4H * HH;
        const bf16* whhl = whhlo + (size_t)l * G4H * HH;
        const float* bl_ = bcomb + (size_t)l * G4H;

        // input GEMM: t=0 rows -> fused cell into oh/ol; t>0 rows -> gx (+bias)
        gemm_bf16<3><<<dim3(G4H / 128, TB / 128, 1), 256, SMEM_BYTES>>>(
            ih, il, wihh, wihl, bl_,
            gx, oh, ol, c, TB, G4H, HH, 1);

        // persistent recurrent: steps 1..9 with internal grid barriers
        rec_layer<<<dim3(G4H / 128, BB / 128, 1), 256, RSMEM_BYTES>>>(
            oh, ol, whhh, whhl, gx, c, ctr + l * 8);
    }

    // final activations in xA (10 layers, even count)
    pack_split<<<(BB * KFC1 + EL - 1) / EL, EL>>>(xAhi, xAlo, xcathi, xcatlo);

    // fc1 split-K partials + reduce
    gemm_bf16<4><<<dim3(HH / 128, BB / 128, SPLITK), 256, SMEM_BYTES>>>(
        xcathi, xcatlo, fc1whi, fc1wlo, nullptr,
        part, nullptr, nullptr, nullptr, BB, HH, KFC1, SPLITK);
    reduce_fc1<<<(BB * HH + EL - 1) / EL, EL>>>(part, fc1_b, out);
}